// round 5
// baseline (speedup 1.0000x reference)
#include <cuda_runtime.h>
#include <cstdint>

// out[b,d,k] = sum_e S[k,d,e] * (x[b,e,k] - mu[e,k])
// B=8192, D=E=64, K=128. fp32.
// R5: R4 was issue/latency-bound at 2 warps/SMSP. Go to 512 threads
// (4 warps/SMSP) with a halved per-thread tile (8d x 2b x packed-k2,
// 16 ull accs = 32 regs) so we stay far from the 128-reg cap.
// Same structure: S swizzled in SMEM, x staged via double-buffered cp.async,
// mu folded into -c = -S@mu.

using ull = unsigned long long;

#define NBY 9            // 16 k-tiles x 9 = 144 CTAs (~1 wave)
#define NBT 256          // 8192 / 32 b per tile

__device__ __forceinline__ void ffma2(ull &d, ull a, ull b) {
    asm("fma.rn.f32x2 %0, %1, %2, %0;" : "+l"(d) : "l"(a), "l"(b));
}
__device__ __forceinline__ void cpa8(uint32_t dst, const float* src) {
    asm volatile("cp.async.ca.shared.global [%0], [%1], 8;" :: "r"(dst), "l"(src));
}
__device__ __forceinline__ void cpa_commit() {
    asm volatile("cp.async.commit_group;");
}
__device__ __forceinline__ void cpa_wait1() {
    asm volatile("cp.async.wait_group 1;");
}

__global__ __launch_bounds__(512, 1)
void cluster_norm_kernel(const float* __restrict__ x,
                         const float* __restrict__ mu,
                         const float* __restrict__ S,
                         float* __restrict__ out)
{
    extern __shared__ float smem_f[];
    float* Sf = smem_f;            // 32768 floats : swizzled S tile (128KB)
    float* Cf = smem_f + 32768;    // 512 floats   : -c[d,kpair]
    float* Xf = smem_f + 33280;    // 2 x 8192 floats : x half-tile double buffer

    const int tid   = threadIdx.x;
    const int kt    = blockIdx.x;       // 0..15
    const int kbase = kt * 8;
    const int by    = blockIdx.y;

    // ---- Stage S tile: S[kbase+kl][d][e] -> swizzled SMEM ----
    // float idx: e*512 + (d>>1)*16 + (kl>>1)*4 + (d&1)*2 + (kl&1)
    // one 16B slot = (d0k0, d0k1, d1k0, d1k1) for a (d-pair, k-pair).
    for (int g = tid; g < 8192; g += 512) {
        int kl = g >> 10;
        int d  = (g >> 4) & 63;
        int e4 = g & 15;
        const float4 v = *(const float4*)(S + (size_t)(kbase + kl) * 4096 + d * 64 + e4 * 4);
        int base = (d >> 1) * 16 + (kl >> 1) * 4 + (d & 1) * 2 + (kl & 1);
        int e0 = e4 * 4;
        Sf[(e0 + 0) * 512 + base] = v.x;
        Sf[(e0 + 1) * 512 + base] = v.y;
        Sf[(e0 + 2) * 512 + base] = v.z;
        Sf[(e0 + 3) * 512 + base] = v.w;
    }
    __syncthreads();

    // ---- -c[d,kpair] = -sum_e S[k,d,e]*mu[e,k] ----
    if (tid < 128) {
        int kp = tid & 3, dp = tid >> 2;
        int k0c = kbase + kp * 2;
        float4 c = make_float4(0.f, 0.f, 0.f, 0.f);
        const float4* S4 = (const float4*)Sf;
        #pragma unroll 4
        for (int e = 0; e < 64; e++) {
            float4 sv = S4[e * 128 + dp * 4 + kp];
            float m0 = mu[e * 128 + k0c];
            float m1 = mu[e * 128 + k0c + 1];
            c.x -= sv.x * m0;
            c.y -= sv.y * m1;
            c.z -= sv.z * m0;
            c.w -= sv.w * m1;
        }
        ((float4*)Cf)[tid] = c;
    }
    __syncthreads();

    // Thread decomposition (512 threads, 16 warps):
    //   kp  = tid & 3          k-pair (lanes 0-3)
    //   bl  = (tid>>2) & 7     b-lane within warp (8 lanes broadcast S)
    //   w   = tid >> 5         warp id
    //   dg  = w & 7            d-group of 8 (8 groups x 8 = 64 d)
    //   bh  = w >> 3           b high bit (blo = bh*8 + bl in 0..15)
    // Thread handles b = {btile*32 + blo, +16}, d = dg*8 .. dg*8+7, k-pair kp.
    const int kp  = tid & 3;
    const int bl  = (tid >> 2) & 7;
    const int w   = tid >> 5;
    const int dg  = w & 7;
    const int bh  = w >> 3;
    const int blo = bh * 8 + bl;            // 0..15
    const int k0  = kbase + kp * 2;

    const ulonglong2* S2 = (const ulonglong2*)Sf;
    const ulonglong2* C2 = (const ulonglong2*)Cf;

    // cp.async half-tile loader: 8192 floats = 4096 x 8B granules, 8/thread.
    // granule o: kp_o=o&3, e2=(o>>2)&31, bl_o=(o>>7)&15, bsel=(o>>11)&1
    // smem float idx: e2*256 + bl_o*16 + kp_o*4 + bsel*2
    auto load_half = [&](int buf, int bt, int eh) {
        uint32_t xsh = (uint32_t)__cvta_generic_to_shared(Xf + buf * 8192);
        #pragma unroll
        for (int i = 0; i < 8; i++) {
            int o    = tid + 512 * i;
            int kpo  = o & 3;
            int e2   = (o >> 2) & 31;
            int blo2 = (o >> 7) & 15;
            int bs   = (o >> 11) & 1;
            int b    = bt * 32 + blo2 + bs * 16;
            int e    = eh * 32 + e2;
            const float* src = x + (size_t)b * 8192 + (size_t)e * 128 + kbase + kpo * 2;
            uint32_t dst = xsh + (uint32_t)(e2 * 256 + blo2 * 16 + kpo * 4 + bs * 2) * 4u;
            cpa8(dst, src);
        }
        cpa_commit();
    };

    int lb = by, lh = 0;
    auto advance = [&]() {
        lh ^= 1;
        if (lh == 0) { lb += NBY; if (lb >= NBT) lb = by; }
    };

    load_half(0, lb, lh);
    advance();
    int cur = 0;

    for (int bt = by; bt < NBT; bt += NBY) {
        const int b0 = bt * 32 + blo;       // second b is b0 + 16

        // init accumulators to -c ; d-pair p = dg*4 + j
        ull acc0[8], acc1[8];
        #pragma unroll
        for (int j = 0; j < 4; j++) {
            ulonglong2 cc = C2[(dg * 4 + j) * 4 + kp];
            acc0[2*j] = cc.x;  acc0[2*j+1] = cc.y;
            acc1[2*j] = cc.x;  acc1[2*j+1] = cc.y;
        }

        #pragma unroll
        for (int h = 0; h < 2; h++) {
            load_half(cur ^ 1, lb, lh);     // issue next half
            advance();
            cpa_wait1();                    // current half done
            __syncthreads();

            const ulonglong2* xb  = (const ulonglong2*)(Xf + cur * 8192) + blo * 4 + kp;
            const ulonglong2* sp0 = S2 + (h * 32) * 128 + dg * 16 + kp;
            #pragma unroll 4
            for (int e2 = 0; e2 < 32; e2++) {
                ulonglong2 xv = xb[e2 * 64];        // (x_b0 kpair, x_b1 kpair)
                const ulonglong2* sp = sp0 + e2 * 128;
                #pragma unroll
                for (int j = 0; j < 4; j++) {
                    ulonglong2 s = sp[j * 4];       // broadcast x8 over bl
                    ffma2(acc0[2*j],   s.x, xv.x);
                    ffma2(acc0[2*j+1], s.y, xv.x);
                    ffma2(acc1[2*j],   s.x, xv.y);
                    ffma2(acc1[2*j+1], s.y, xv.y);
                }
            }
            __syncthreads();                // readers done before buf reuse
            cur ^= 1;
        }

        float* op0 = out + (size_t)b0 * 8192 + k0;
        float* op1 = op0 + (size_t)16 * 8192;
        #pragma unroll
        for (int j = 0; j < 4; j++) {
            const int d0 = dg * 8 + j * 2;
            *(ull*)(op0 + (size_t)d0 * 128)     = acc0[2*j];
            *(ull*)(op0 + (size_t)(d0+1) * 128) = acc0[2*j+1];
            *(ull*)(op1 + (size_t)d0 * 128)     = acc1[2*j];
            *(ull*)(op1 + (size_t)(d0+1) * 128) = acc1[2*j+1];
        }
    }
}

extern "C" void kernel_launch(void* const* d_in, const int* in_sizes, int n_in,
                              void* d_out, int out_size)
{
    const float* x  = (const float*)d_in[0];   // [8192, 64, 128]
    const float* mu = (const float*)d_in[1];   // [64, 128]
    const float* S  = (const float*)d_in[2];   // [128, 64, 64]
    float* out      = (float*)d_out;           // [8192, 64, 128]

    const int smem_bytes = (32768 + 512 + 2 * 8192) * sizeof(float);  // 198656
    cudaFuncSetAttribute(cluster_norm_kernel,
                         cudaFuncAttributeMaxDynamicSharedMemorySize, smem_bytes);

    dim3 grid(16, NBY);
    cluster_norm_kernel<<<grid, 512, smem_bytes>>>(x, mu, S, out);
}

// round 7
// speedup vs baseline: 1.4253x; 1.4253x over previous
#include <cuda_runtime.h>
#include <cuda_fp16.h>
#include <cstdint>

// out[b,d,k] = sum_e S[k,d,e] * (x[b,e,k] - mu[e,k])
// B=8192, D=E=64, K=128. fp32 in/out.
// R7: generic-PTX tensor cores (ldmatrix + mma.sync.m16n8k16.f16.f32),
// since sm_103a-only tcgen05 is unavailable (harness targets sm_103 generic).
// CTA = 8 k x 64 b. S -> fp16 B[e][d] tiles; x-mu (fp32) -> fp16 A[b][e] tiles.
// Warp = (kq,bq,dh): 4 k x 16 b x 32 d, fp32 accum in regs.
// Epilogue transposes through smem so stores are full 32B sectors (8 k contig).

#define NBY 9

static constexpr int AOFF   = 0;        // 8 x 8KB A tiles (also Dbuf low half)
static constexpr int BOFF   = 131072;   // 8 x 8KB B tiles
static constexpr int MUOFF  = 196608;   // 2KB mu tile
static constexpr int SMEM_BYTES = 198656;
// Dbuf = [0, 131072): [64 b][64 d][8 k] fp32 (overlaps A + scratch; B preserved)

__device__ __forceinline__ uint32_t cvt2(float hi, float lo) {
    uint32_t r;
    asm("cvt.rn.f16x2.f32 %0, %1, %2;" : "=r"(r) : "f"(hi), "f"(lo));
    return r;
}

__device__ __forceinline__ void ldm_x4(uint32_t& r0, uint32_t& r1, uint32_t& r2,
                                       uint32_t& r3, uint32_t addr) {
    asm volatile("ldmatrix.sync.aligned.m8n8.x4.shared.b16 {%0,%1,%2,%3}, [%4];"
                 : "=r"(r0), "=r"(r1), "=r"(r2), "=r"(r3) : "r"(addr));
}
__device__ __forceinline__ void ldm_x4t(uint32_t& r0, uint32_t& r1, uint32_t& r2,
                                        uint32_t& r3, uint32_t addr) {
    asm volatile("ldmatrix.sync.aligned.m8n8.x4.trans.shared.b16 {%0,%1,%2,%3}, [%4];"
                 : "=r"(r0), "=r"(r1), "=r"(r2), "=r"(r3) : "r"(addr));
}
__device__ __forceinline__ void mma16816(float& d0, float& d1, float& d2, float& d3,
                                         uint32_t a0, uint32_t a1, uint32_t a2, uint32_t a3,
                                         uint32_t b0, uint32_t b1) {
    asm volatile(
        "mma.sync.aligned.m16n8k16.row.col.f32.f16.f16.f32 "
        "{%0,%1,%2,%3}, {%4,%5,%6,%7}, {%8,%9}, {%0,%1,%2,%3};"
        : "+f"(d0), "+f"(d1), "+f"(d2), "+f"(d3)
        : "r"(a0), "r"(a1), "r"(a2), "r"(a3), "r"(b0), "r"(b1));
}

__global__ __launch_bounds__(512, 1)
void cluster_norm_mma_kernel(const float* __restrict__ x,
                             const float* __restrict__ mu,
                             const float* __restrict__ S,
                             float* __restrict__ out)
{
    extern __shared__ char smem[];
    const uint32_t sb = (uint32_t)__cvta_generic_to_shared(smem);
    const int tid   = threadIdx.x;
    const int lane  = tid & 31;
    const int w     = tid >> 5;
    const int kbase = blockIdx.x * 8;

    // ---- mu tile: Mu[e][8k] fp32 ----
    if (tid < 128) {
        int e = tid >> 1, h = tid & 1;
        float4 v = *(const float4*)(mu + e * 128 + kbase + h * 4);
        *(float4*)(smem + MUOFF + e * 32 + h * 16) = v;
    }

    // ---- S -> fp16 B tiles: Bk[e][d] halves, rows 128B, slot^=(e&7) ----
    #pragma unroll 4
    for (int i = 0; i < 32; i++) {
        int o  = tid + 512 * i;
        int e  = o & 63;
        int dp = (o >> 6) & 31;
        int k  = o >> 11;
        const float* sp = S + (size_t)(kbase + k) * 4096 + (size_t)(dp * 2) * 64 + e;
        float s0 = sp[0];
        float s1 = sp[64];
        uint32_t h2 = cvt2(s1, s0);   // lo = even d
        uint32_t a = sb + BOFF + k * 8192 + e * 128
                   + ((((uint32_t)(dp >> 2)) ^ (uint32_t)(e & 7)) << 4) + (dp & 3) * 4;
        asm volatile("st.shared.b32 [%0], %1;" :: "r"(a), "r"(h2) : "memory");
    }
    __syncthreads();

    // warp tile: kq = w&1 (4 k), bq = (w>>1)&3 (16 b), dh = w>>3 (32 d)
    const int kq = w & 1;
    const int bq = (w >> 1) & 3;
    const int dh = w >> 3;
    const int l15 = lane & 15;
    const int lhi = lane >> 4;
    const int rA  = bq * 16 + l15;         // A ldmatrix row (b)
    const int g   = lane >> 2;
    const int tg  = lane & 3;

    for (int bt = blockIdx.y; bt < 128; bt += NBY) {
        const int b0 = bt * 64;

        // ======= Phase 1: stage A tiles: Ak[b][e] halves, slot^=(b&7) =======
        #pragma unroll
        for (int i = 0; i < 4; i++) {
            int o  = tid + 512 * i;
            int et = o & 31;           // e-pair
            int b  = o >> 5;           // 0..63
            const float* xp = x + (size_t)(b0 + b) * 8192 + (size_t)(2 * et) * 128 + kbase;
            float4 xa0 = *(const float4*)(xp);
            float4 xa1 = *(const float4*)(xp + 4);
            float4 xb0 = *(const float4*)(xp + 128);
            float4 xb1 = *(const float4*)(xp + 132);
            const float* mp = (const float*)(smem + MUOFF) + et * 16;
            float4 ma0 = *(const float4*)(mp);
            float4 ma1 = *(const float4*)(mp + 4);
            float4 mb0 = *(const float4*)(mp + 8);
            float4 mb1 = *(const float4*)(mp + 12);
            float da[8], db[8];
            da[0] = xa0.x - ma0.x; da[1] = xa0.y - ma0.y;
            da[2] = xa0.z - ma0.z; da[3] = xa0.w - ma0.w;
            da[4] = xa1.x - ma1.x; da[5] = xa1.y - ma1.y;
            da[6] = xa1.z - ma1.z; da[7] = xa1.w - ma1.w;
            db[0] = xb0.x - mb0.x; db[1] = xb0.y - mb0.y;
            db[2] = xb0.z - mb0.z; db[3] = xb0.w - mb0.w;
            db[4] = xb1.x - mb1.x; db[5] = xb1.y - mb1.y;
            db[6] = xb1.z - mb1.z; db[7] = xb1.w - mb1.w;
            uint32_t base = sb + AOFF + b * 128
                          + ((((uint32_t)(et >> 2)) ^ (uint32_t)(b & 7)) << 4) + (et & 3) * 4;
            #pragma unroll
            for (int k = 0; k < 8; k++) {
                uint32_t h2 = cvt2(db[k], da[k]);   // lo = even e
                asm volatile("st.shared.b32 [%0], %1;"
                             :: "r"(base + (uint32_t)(k * 8192)), "r"(h2) : "memory");
            }
        }
        __syncthreads();

        // ======= Phase 2: MMAs =======
        float D[4][16];
        #pragma unroll
        for (int a = 0; a < 4; a++)
            #pragma unroll
            for (int j = 0; j < 16; j++) D[a][j] = 0.f;

        #pragma unroll
        for (int kk = 0; kk < 4; kk++) {
            const int k = kq * 4 + kk;
            const uint32_t Ab = sb + AOFF + k * 8192;
            const uint32_t Bb = sb + BOFF + k * 8192;
            #pragma unroll
            for (int es = 0; es < 4; es++) {
                uint32_t a0, a1, a2, a3;
                uint32_t aaddr = Ab + rA * 128
                               + ((((uint32_t)(es * 2 + lhi)) ^ (uint32_t)(rA & 7)) << 4);
                ldm_x4(a0, a1, a2, a3, aaddr);
                const int rB = es * 16 + l15;
                const uint32_t brow = Bb + rB * 128;
                #pragma unroll
                for (int ncp = 0; ncp < 2; ncp++) {
                    const int nc = dh * 4 + ncp * 2;
                    uint32_t b0r, b1r, b2r, b3r;
                    uint32_t baddr = brow
                        + ((((uint32_t)(nc + lhi)) ^ (uint32_t)(rB & 7)) << 4);
                    ldm_x4t(b0r, b1r, b2r, b3r, baddr);
                    mma16816(D[kk][ncp*8+0], D[kk][ncp*8+1], D[kk][ncp*8+2], D[kk][ncp*8+3],
                             a0, a1, a2, a3, b0r, b1r);
                    mma16816(D[kk][ncp*8+4], D[kk][ncp*8+5], D[kk][ncp*8+6], D[kk][ncp*8+7],
                             a0, a1, a2, a3, b2r, b3r);
                }
            }
        }
        __syncthreads();   // all mma reads of A done before Dbuf overwrites it

        // ======= Phase 3: D -> Dbuf[b][d][8k] (STS.128 over warp's 4 k) =======
        #pragma unroll
        for (int ncl = 0; ncl < 4; ncl++) {
            #pragma unroll
            for (int j = 0; j < 4; j++) {
                const int bb = bq * 16 + g + ((j & 2) ? 8 : 0);
                const int d  = dh * 32 + ncl * 8 + tg * 2 + (j & 1);
                const uint32_t slot = (uint32_t)(d * 2 + kq) ^ (uint32_t)(bb & 7);
                const uint32_t addr = sb + (uint32_t)(bb * 2048) + (slot << 4);
                asm volatile("st.shared.v4.f32 [%0], {%1,%2,%3,%4};"
                             :: "r"(addr),
                                "f"(D[0][ncl*4+j]), "f"(D[1][ncl*4+j]),
                                "f"(D[2][ncl*4+j]), "f"(D[3][ncl*4+j]) : "memory");
            }
        }
        __syncthreads();

        // ======= Phase 4: coalesced store (32B granules, full sectors) =======
        #pragma unroll
        for (int i = 0; i < 8; i++) {
            int gx = tid + 512 * i;
            int bb = gx >> 6;
            int d  = gx & 63;
            uint32_t s0 = ((uint32_t)(d * 2))     ^ (uint32_t)(bb & 7);
            uint32_t s1 = ((uint32_t)(d * 2 + 1)) ^ (uint32_t)(bb & 7);
            float4 f0, f1;
            asm volatile("ld.shared.v4.f32 {%0,%1,%2,%3}, [%4];"
                         : "=f"(f0.x), "=f"(f0.y), "=f"(f0.z), "=f"(f0.w)
                         : "r"(sb + (uint32_t)(bb * 2048) + (s0 << 4)));
            asm volatile("ld.shared.v4.f32 {%0,%1,%2,%3}, [%4];"
                         : "=f"(f1.x), "=f"(f1.y), "=f"(f1.z), "=f"(f1.w)
                         : "r"(sb + (uint32_t)(bb * 2048) + (s1 << 4)));
            float* op = out + (size_t)(b0 + bb) * 8192 + (size_t)d * 128 + kbase;
            *(float4*)(op)     = f0;
            *(float4*)(op + 4) = f1;
        }
        __syncthreads();   // Dbuf readers done before next A staging
    }
}

extern "C" void kernel_launch(void* const* d_in, const int* in_sizes, int n_in,
                              void* d_out, int out_size)
{
    const float* x  = (const float*)d_in[0];   // [8192, 64, 128]
    const float* mu = (const float*)d_in[1];   // [64, 128]
    const float* S  = (const float*)d_in[2];   // [128, 64, 64]
    float* out      = (float*)d_out;           // [8192, 64, 128]

    cudaFuncSetAttribute(cluster_norm_mma_kernel,
                         cudaFuncAttributeMaxDynamicSharedMemorySize, SMEM_BYTES);

    dim3 grid(16, NBY);
    cluster_norm_mma_kernel<<<grid, 512, SMEM_BYTES>>>(x, mu, S, out);
}

// round 9
// speedup vs baseline: 2.2515x; 1.5797x over previous
#include <cuda_runtime.h>
#include <cuda_fp16.h>
#include <cstdint>

// out[b,d,k] = sum_e S[k,d,e] * (x[b,e,k] - mu[e,k])
// B=8192, D=E=64, K=128. fp32 in/out.
// R9 = R8 with the phase-1 bug fixed: ep must span 32 e-pairs (R8 only wrote
// e<32, leaving garbage fp16 in the upper half of the A tiles -> NaN).
//  - CTA = 8 k x 32 b, 256 threads, smem 96KB -> 2 CTAs/SM overlap phases.
//  - paired-lane 16B global accesses (lane pairs cover one 32B granule).
//  - mu preloaded to registers (thread's (kh,ep) fixed across b-tiles).
//  - epilogue transpose in two 32-d passes through the A region.

#define NBY 18

static constexpr int AOFF   = 0;        // 8 x 4KB A tiles; doubles as Dbuf (32KB)
static constexpr int BOFF   = 32768;    // 8 x 8KB B tiles (64KB)
static constexpr int SMEM_BYTES = 98304;

__device__ __forceinline__ uint32_t cvt2(float hi, float lo) {
    uint32_t r;
    asm("cvt.rn.f16x2.f32 %0, %1, %2;" : "=r"(r) : "f"(hi), "f"(lo));
    return r;
}
__device__ __forceinline__ void ldm_x4(uint32_t& r0, uint32_t& r1, uint32_t& r2,
                                       uint32_t& r3, uint32_t addr) {
    asm volatile("ldmatrix.sync.aligned.m8n8.x4.shared.b16 {%0,%1,%2,%3}, [%4];"
                 : "=r"(r0), "=r"(r1), "=r"(r2), "=r"(r3) : "r"(addr));
}
__device__ __forceinline__ void ldm_x4t(uint32_t& r0, uint32_t& r1, uint32_t& r2,
                                        uint32_t& r3, uint32_t addr) {
    asm volatile("ldmatrix.sync.aligned.m8n8.x4.trans.shared.b16 {%0,%1,%2,%3}, [%4];"
                 : "=r"(r0), "=r"(r1), "=r"(r2), "=r"(r3) : "r"(addr));
}
__device__ __forceinline__ void mma16816(float& d0, float& d1, float& d2, float& d3,
                                         uint32_t a0, uint32_t a1, uint32_t a2, uint32_t a3,
                                         uint32_t b0, uint32_t b1) {
    asm volatile(
        "mma.sync.aligned.m16n8k16.row.col.f32.f16.f16.f32 "
        "{%0,%1,%2,%3}, {%4,%5,%6,%7}, {%8,%9}, {%0,%1,%2,%3};"
        : "+f"(d0), "+f"(d1), "+f"(d2), "+f"(d3)
        : "r"(a0), "r"(a1), "r"(a2), "r"(a3), "r"(b0), "r"(b1));
}

__global__ __launch_bounds__(256, 2)
void cluster_norm_mma_kernel(const float* __restrict__ x,
                             const float* __restrict__ mu,
                             const float* __restrict__ S,
                             float* __restrict__ out)
{
    extern __shared__ char smem[];
    const uint32_t sb = (uint32_t)__cvta_generic_to_shared(smem);
    const int tid   = threadIdx.x;
    const int lane  = tid & 31;
    const int w     = tid >> 5;
    const int kbase = blockIdx.x * 8;

    // ---- S -> fp16 B tiles: Bk[e][d], rows 128B, slot ^= (e&7) ----
    #pragma unroll 4
    for (int i = 0; i < 64; i++) {
        int o  = tid + 256 * i;
        int e  = o & 63;
        int dp = (o >> 6) & 31;
        int k  = o >> 11;
        const float* sp = S + (size_t)(kbase + k) * 4096 + (size_t)(dp * 2) * 64 + e;
        float s0 = sp[0];
        float s1 = sp[64];
        uint32_t h2 = cvt2(s1, s0);   // lo = even d
        uint32_t a = sb + BOFF + k * 8192 + e * 128
                   + ((((uint32_t)(dp >> 2)) ^ (uint32_t)(e & 7)) << 4) + (dp & 3) * 4;
        asm volatile("st.shared.b32 [%0], %1;" :: "r"(a), "r"(h2) : "memory");
    }

    // ---- thread's fixed (kh, ep) + mu register preload ----
    // kh = tid&1 (k-half), ep = (tid>>1)&31 (e-pair), bbase = tid>>6 (0..3)
    const int kh    = tid & 1;
    const int ep    = (tid >> 1) & 31;
    const int bbase = tid >> 6;
    float4 m0 = *(const float4*)(mu + (size_t)(2 * ep) * 128 + kbase + kh * 4);
    float4 m1 = *(const float4*)(mu + (size_t)(2 * ep + 1) * 128 + kbase + kh * 4);
    __syncthreads();

    // warp tile: kq = w&1 (4 k), bq = (w>>1)&1 (16 b), dh = w>>2 (32 d)
    const int kq  = w & 1;
    const int bq  = (w >> 1) & 1;
    const int dh  = w >> 2;
    const int l15 = lane & 15;
    const int lhi = lane >> 4;
    const int rA  = bq * 16 + l15;
    const int g   = lane >> 2;
    const int tg  = lane & 3;

    for (int bt = blockIdx.y; bt < 256; bt += NBY) {
        const int b0 = bt * 32;

        // ======= Phase 1: x - mu -> fp16 A tiles =======
        // 2048 tasks = 32 b x 32 ep x 2 kh; thread: fixed (kh,ep), b = bbase+4i.
        #pragma unroll
        for (int i = 0; i < 8; i++) {
            const int b = bbase + 4 * i;
            const float* xp = x + (size_t)(b0 + b) * 8192 + (size_t)(2 * ep) * 128
                            + kbase + kh * 4;
            float4 xa = *(const float4*)(xp);        // e = 2ep,   k kh*4..+3
            float4 xb = *(const float4*)(xp + 128);  // e = 2ep+1
            float va[4], vb[4];
            va[0] = xa.x - m0.x; va[1] = xa.y - m0.y;
            va[2] = xa.z - m0.z; va[3] = xa.w - m0.w;
            vb[0] = xb.x - m1.x; vb[1] = xb.y - m1.y;
            vb[2] = xb.z - m1.z; vb[3] = xb.w - m1.w;
            uint32_t base = sb + AOFF + b * 128
                          + ((((uint32_t)(ep >> 2)) ^ (uint32_t)(b & 7)) << 4)
                          + (ep & 3) * 4;
            #pragma unroll
            for (int j = 0; j < 4; j++) {
                uint32_t h2 = cvt2(vb[j], va[j]);    // lo = even e
                asm volatile("st.shared.b32 [%0], %1;"
                             :: "r"(base + (uint32_t)((kh * 4 + j) * 4096)), "r"(h2)
                             : "memory");
            }
        }
        __syncthreads();

        // ======= Phase 2: MMAs =======
        float D[4][16];
        #pragma unroll
        for (int a = 0; a < 4; a++)
            #pragma unroll
            for (int j = 0; j < 16; j++) D[a][j] = 0.f;

        #pragma unroll
        for (int kk = 0; kk < 4; kk++) {
            const int k = kq * 4 + kk;
            const uint32_t Ab = sb + AOFF + k * 4096;
            const uint32_t Bb = sb + BOFF + k * 8192;
            #pragma unroll
            for (int es = 0; es < 4; es++) {
                uint32_t a0, a1, a2, a3;
                uint32_t aaddr = Ab + rA * 128
                               + ((((uint32_t)(es * 2 + lhi)) ^ (uint32_t)(rA & 7)) << 4);
                ldm_x4(a0, a1, a2, a3, aaddr);
                const int rB = es * 16 + l15;
                const uint32_t brow = Bb + rB * 128;
                #pragma unroll
                for (int ncp = 0; ncp < 2; ncp++) {
                    const int nc = dh * 4 + ncp * 2;
                    uint32_t b0r, b1r, b2r, b3r;
                    uint32_t baddr = brow
                        + ((((uint32_t)(nc + lhi)) ^ (uint32_t)(rB & 7)) << 4);
                    ldm_x4t(b0r, b1r, b2r, b3r, baddr);
                    mma16816(D[kk][ncp*8+0], D[kk][ncp*8+1], D[kk][ncp*8+2], D[kk][ncp*8+3],
                             a0, a1, a2, a3, b0r, b1r);
                    mma16816(D[kk][ncp*8+4], D[kk][ncp*8+5], D[kk][ncp*8+6], D[kk][ncp*8+7],
                             a0, a1, a2, a3, b2r, b3r);
                }
            }
        }
        __syncthreads();   // all mma reads of A done before Dbuf overwrites it

        // ======= Phase 3+4: two 32-d passes through Dbuf (= A region) =======
        // Dbuf: row dl (0..31) x 1024B; slot16 = (bb*2 + khalf) ^ (dl&7)
        #pragma unroll
        for (int p = 0; p < 2; p++) {
            if (dh == p) {
                #pragma unroll
                for (int ncl = 0; ncl < 4; ncl++) {
                    #pragma unroll
                    for (int j = 0; j < 4; j++) {
                        const int bb = bq * 16 + g + ((j & 2) ? 8 : 0);
                        const int dl = ncl * 8 + tg * 2 + (j & 1);
                        const uint32_t slot = (uint32_t)(bb * 2 + kq) ^ (uint32_t)(dl & 7);
                        const uint32_t addr = sb + (uint32_t)(dl * 1024) + (slot << 4);
                        asm volatile("st.shared.v4.f32 [%0], {%1,%2,%3,%4};"
                                     :: "r"(addr),
                                        "f"(D[0][ncl*4+j]), "f"(D[1][ncl*4+j]),
                                        "f"(D[2][ncl*4+j]), "f"(D[3][ncl*4+j]) : "memory");
                    }
                }
            }
            __syncthreads();

            // coalesced store: o: kh2 = o&1, dl = (o>>1)&31, bb = (o>>6)&31
            #pragma unroll
            for (int i = 0; i < 8; i++) {
                int o   = tid + 256 * i;
                int kh2 = o & 1;
                int dl  = (o >> 1) & 31;
                int bb  = (o >> 6) & 31;
                uint32_t slot = (uint32_t)(bb * 2 + kh2) ^ (uint32_t)(dl & 7);
                float4 f;
                asm volatile("ld.shared.v4.f32 {%0,%1,%2,%3}, [%4];"
                             : "=f"(f.x), "=f"(f.y), "=f"(f.z), "=f"(f.w)
                             : "r"(sb + (uint32_t)(dl * 1024) + (slot << 4)));
                float* op = out + (size_t)(b0 + bb) * 8192
                          + (size_t)(p * 32 + dl) * 128 + kbase + kh2 * 4;
                *(float4*)(op) = f;
            }
            __syncthreads();
        }
    }
}

extern "C" void kernel_launch(void* const* d_in, const int* in_sizes, int n_in,
                              void* d_out, int out_size)
{
    const float* x  = (const float*)d_in[0];   // [8192, 64, 128]
    const float* mu = (const float*)d_in[1];   // [64, 128]
    const float* S  = (const float*)d_in[2];   // [128, 64, 64]
    float* out      = (float*)d_out;           // [8192, 64, 128]

    cudaFuncSetAttribute(cluster_norm_mma_kernel,
                         cudaFuncAttributeMaxDynamicSharedMemorySize, SMEM_BYTES);

    dim3 grid(16, NBY);
    cluster_norm_mma_kernel<<<grid, 256, SMEM_BYTES>>>(x, mu, S, out);
}